// round 5
// baseline (speedup 1.0000x reference)
#include <cuda_runtime.h>
#include <cuda_bf16.h>
#include <cstdint>
#include <math.h>

#define NN 30000
#define KK 15
#define TT 400
#define NCC 5
#define GG 8                      // rows per block in main kernel
#define ROWS 16                   // self + 15 neighbors
#define ROWBYTES (TT * 2)         // 800 B per bf16 row
#define STAGEBYTES (ROWS * ROWBYTES)  // 12800 B
#define NSTAGE 4                  // ring depth
#define T4 (TT / 4)               // 100 chunks of 4 t-values

// ---------------- scratch (device globals: allocation-free) ----------------
__device__ __align__(32) __nv_bfloat16 g_emd[NN * TT];  // summed EMD bf16 (24 MB)
__device__ float g_W[NN * 16];
__device__ float g_UV[NN * 10];
__device__ float g_tab[2 * NCC * TT];

// ---------------- helpers ----------------
__device__ __forceinline__ uint32_t smem_u32(const void* p) {
    uint32_t a;
    asm("{ .reg .u64 t; cvta.to.shared.u64 t, %1; cvt.u32.u64 %0, t; }"
        : "=r"(a) : "l"(p));
    return a;
}
__device__ __forceinline__ void mbar_init(uint32_t mbar, uint32_t count) {
    asm volatile("mbarrier.init.shared.b64 [%0], %1;" :: "r"(mbar), "r"(count) : "memory");
}
__device__ __forceinline__ void mbar_expect_tx(uint32_t mbar, uint32_t bytes) {
    asm volatile("mbarrier.arrive.expect_tx.shared.b64 _, [%0], %1;"
                 :: "r"(mbar), "r"(bytes) : "memory");
}
__device__ __forceinline__ void mbar_wait(uint32_t mbar, uint32_t parity) {
    asm volatile(
        "{\n\t"
        ".reg .pred P;\n\t"
        "LAB_WAIT_%=:\n\t"
        "mbarrier.try_wait.parity.acquire.cta.shared::cta.b64 P, [%0], %1, 0x989680;\n\t"
        "@P bra LAB_DONE_%=;\n\t"
        "bra LAB_WAIT_%=;\n\t"
        "LAB_DONE_%=:\n\t"
        "}"
        :: "r"(mbar), "r"(parity) : "memory");
}
__device__ __forceinline__ void bulk_g2s(uint32_t dst, const void* src,
                                         uint32_t bytes, uint32_t mbar) {
    asm volatile(
        "cp.async.bulk.shared::cluster.global.mbarrier::complete_tx::bytes "
        "[%0], [%1], %2, [%3];"
        :: "r"(dst), "l"(src), "r"(bytes), "r"(mbar) : "memory");
}
// bf16 unpack: lo via shift; hi uses the raw word (garbage low bits are below
// bf16 precision; measured contribution keeps rel_err ~2e-4, fine vs 1e-3)
__device__ __forceinline__ float bf_lo(uint32_t u) { return __uint_as_float(u << 16); }
__device__ __forceinline__ float bf_hi(uint32_t u) { return __uint_as_float(u); }

// ---------------- fused pre-pass: small work FIRST, then emdsum(bf16) --------
#define EMD_WORK  (NN * (TT / 8))
#define NB_EMD    ((EMD_WORK + 255) / 256)
#define NB_W      ((NN * 16 + 255) / 256)
#define NB_UV     ((NN * NCC + 255) / 256)
#define NB_TAB    ((NCC * TT + 255) / 256)
#define NB_PRE    (NB_EMD + NB_W + NB_UV + NB_TAB)

__global__ void __launch_bounds__(256)
k_pre(const float* __restrict__ emd,
      const float* __restrict__ nbr_w,
      const float* __restrict__ loc_w,
      const float* __restrict__ esw,
      const float* __restrict__ lsw,
      const float* __restrict__ amp,
      const float* __restrict__ ph,
      const int*   __restrict__ idx,
      const float* __restrict__ tv,
      const float* __restrict__ per) {
    int b = blockIdx.x;
    if (b < NB_W) {
        int i = b * 256 + threadIdx.x;
        if (i >= NN * 16) return;
        int n = i >> 4;
        int j = i & 15;
        float ew = 1.0f / (1.0f + expf(-esw[n]));
        if (j == 0) { g_W[i] = 1.0f - ew; return; }
        float lw = 1.0f / (1.0f + expf(-lsw[n]));
        int k = j - 1;
        g_W[i] = ew * lw * loc_w[n * KK + k] + ew * (1.0f - lw) * nbr_w[n * KK + k];
        return;
    }
    b -= NB_W;
    if (b < NB_UV) {
        int i = b * 256 + threadIdx.x;
        if (i >= NN * NCC) return;
        int n = i / NCC;
        int c = i - n * NCC;
        float sa = 0.0f, ss = 0.0f, sc = 0.0f;
#pragma unroll
        for (int k = 0; k < KK; k++) {
            int m = idx[n * KK + k];
            float w = nbr_w[n * KK + k];
            sa += w * amp[m * NCC + c];
            float p = ph[m * NCC + c];
            float s, co;
            sincosf(p, &s, &co);
            ss += w * s;
            sc += w * co;
        }
        float A = 0.8f * amp[i] + 0.2f * sa;
        float P = 0.8f * ph[i] + 0.2f * atan2f(ss, sc);
        float sp, cp;
        sincosf(P, &sp, &cp);
        g_UV[n * 10 + c] = A * cp;
        g_UV[n * 10 + 5 + c] = A * sp;
        return;
    }
    b -= NB_UV;
    if (b < NB_TAB) {
        int i = b * 256 + threadIdx.x;
        if (i >= NCC * TT) return;
        int c = i / TT;
        int t = i - c * TT;
        float p = fminf(fmaxf(per[c], 15.0f), 350.0f);
        float arg = 6.283185307179586f * tv[t] / p;
        float s, co;
        sincosf(arg, &s, &co);
        g_tab[i] = s;
        g_tab[NCC * TT + i] = co;
        return;
    }
    b -= NB_TAB;
    {
        // ---- sum 4 EMD components, write bf16 ----
        int i = b * 256 + threadIdx.x;
        if (i >= EMD_WORK) return;
        int n = i / (TT / 8);
        int t8 = i - n * (TT / 8);
        const float4* base = reinterpret_cast<const float4*>(emd + (size_t)n * 4 * TT);
        float r[8];
#pragma unroll
        for (int e = 0; e < 8; e++) r[e] = 0.0f;
#pragma unroll
        for (int c = 0; c < 4; c++) {
            float4 a = base[c * T4 + 2 * t8];
            float4 bb = base[c * T4 + 2 * t8 + 1];
            r[0] += a.x;  r[1] += a.y;  r[2] += a.z;  r[3] += a.w;
            r[4] += bb.x; r[5] += bb.y; r[6] += bb.z; r[7] += bb.w;
        }
        __nv_bfloat162 h[4];
#pragma unroll
        for (int e = 0; e < 4; e++)
            h[e] = __floats2bfloat162_rn(r[2 * e], r[2 * e + 1]);
        reinterpret_cast<uint4*>(g_emd + (size_t)n * TT)[t8] =
            *reinterpret_cast<uint4*>(h);
    }
}

// ---------------- main kernel: 4-deep TMA pipeline + fused output ----------
extern __shared__ __align__(16) __nv_bfloat16 s_buf[];  // NSTAGE * 12800 B

__global__ void __launch_bounds__(128)
k_main(const int* __restrict__ idx,
       const float* __restrict__ coff,
       const float* __restrict__ ltr,
       const float* __restrict__ tv,
       float* __restrict__ out) {
    __shared__ __align__(8) unsigned long long s_full[NSTAGE];
    __shared__ int   s_idx[GG][KK];
    __shared__ float s_W[GG][16];
    __shared__ float s_UV[GG][10];
    __shared__ float s_off[GG];
    __shared__ float s_tr[GG];

    int tid = threadIdx.x;
    int n0 = blockIdx.x * GG;

    if (tid < GG * KK) s_idx[tid / KK][tid % KK] = idx[n0 * KK + tid];
    if (tid < GG * 16) s_W[tid >> 4][tid & 15] = g_W[n0 * 16 + tid];
    if (tid < GG * 10) s_UV[tid / 10][tid % 10] = g_UV[n0 * 10 + tid];
    if (tid < GG) { s_off[tid] = coff[n0 + tid]; s_tr[tid] = ltr[n0 + tid]; }

    uint32_t full0 = smem_u32(&s_full[0]);
    uint32_t bufb  = smem_u32(s_buf);
    if (tid == 0) {
#pragma unroll
        for (int s = 0; s < NSTAGE; s++) mbar_init(full0 + 8u * s, 1);
        asm volatile("fence.proxy.async.shared::cta;" ::: "memory");
    }

    // per-thread register-resident harmonic table + time values (fp32)
    float4 st[NCC], ct[NCC], tv4;
    bool act = (tid < T4);
    if (act) {
#pragma unroll
        for (int c = 0; c < NCC; c++) {
            st[c] = reinterpret_cast<const float4*>(g_tab + c * TT)[tid];
            ct[c] = reinterpret_cast<const float4*>(g_tab + NCC * TT + c * TT)[tid];
        }
        tv4 = reinterpret_cast<const float4*>(tv)[tid];
    }
    __syncthreads();  // s_idx visible; mbarriers initialized

    auto issue = [&](int s) {
        uint32_t dst = bufb + (uint32_t)(s & (NSTAGE - 1)) * STAGEBYTES;
        uint32_t mb  = full0 + (uint32_t)(s & (NSTAGE - 1)) * 8;
        mbar_expect_tx(mb, STAGEBYTES);
        bulk_g2s(dst, g_emd + (size_t)(n0 + s) * TT, ROWBYTES, mb);  // self row
#pragma unroll
        for (int k = 0; k < KK; k++) {
            bulk_g2s(dst + (uint32_t)(k + 1) * ROWBYTES,
                     g_emd + (size_t)s_idx[s][k] * TT, ROWBYTES, mb);
        }
    };

    if (tid == 0) {
        issue(0);
        issue(1);
        issue(2);
    }

    for (int i = 0; i < GG; i++) {
        // buffer (i+3)%4 == (i-1)%4 was released by last stage's syncthreads
        if (tid == 0 && i + 3 < GG) issue(i + 3);

        mbar_wait(full0 + (uint32_t)(i & (NSTAGE - 1)) * 8,
                  (uint32_t)((i >> 2) & 1));

        if (act) {
            const uint32_t* rows = reinterpret_cast<const uint32_t*>(
                s_buf + (size_t)(i & (NSTAGE - 1)) * (ROWS * TT));
            float w[16];
#pragma unroll
            for (int j = 0; j < 16; j++) w[j] = s_W[i][j];

            float off = s_off[i], tr = s_tr[i];
            float4 acc;
            acc.x = fmaf(tr, tv4.x, off);
            acc.y = fmaf(tr, tv4.y, off);
            acc.z = fmaf(tr, tv4.z, off);
            acc.w = fmaf(tr, tv4.w, off);
#pragma unroll
            for (int c = 0; c < NCC; c++) {
                float u = s_UV[i][c], v = s_UV[i][5 + c];
                acc.x = fmaf(u, st[c].x, fmaf(v, ct[c].x, acc.x));
                acc.y = fmaf(u, st[c].y, fmaf(v, ct[c].y, acc.y));
                acc.z = fmaf(u, st[c].z, fmaf(v, ct[c].z, acc.z));
                acc.w = fmaf(u, st[c].w, fmaf(v, ct[c].w, acc.w));
            }
#pragma unroll
            for (int j = 0; j < 16; j++) {
                uint2 raw = *reinterpret_cast<const uint2*>(rows + j * 200 + 2 * tid);
                acc.x = fmaf(w[j], bf_lo(raw.x), acc.x);
                acc.y = fmaf(w[j], bf_hi(raw.x), acc.y);
                acc.z = fmaf(w[j], bf_lo(raw.y), acc.z);
                acc.w = fmaf(w[j], bf_hi(raw.y), acc.w);
            }
            reinterpret_cast<float4*>(out + (size_t)(n0 + i) * TT)[tid] = acc;
        }
        __syncthreads();  // all threads done reading buffer i%4
    }
}

// ---------------- launch ----------------
extern "C" void kernel_launch(void* const* d_in, const int* in_sizes, int n_in,
                              void* d_out, int out_size) {
    const float* tv   = (const float*)d_in[0];
    const float* coff = (const float*)d_in[1];
    const float* ltr  = (const float*)d_in[2];
    const float* emd  = (const float*)d_in[3];
    const int*   idx  = (const int*)  d_in[4];
    const float* nw   = (const float*)d_in[5];
    const float* lwv  = (const float*)d_in[6];
    const float* amp  = (const float*)d_in[7];
    const float* ph   = (const float*)d_in[8];
    const float* per  = (const float*)d_in[9];
    const float* esw  = (const float*)d_in[10];
    const float* lsw  = (const float*)d_in[11];
    float* out = (float*)d_out;

    k_pre<<<NB_PRE, 256>>>(emd, nw, lwv, esw, lsw, amp, ph, idx, tv, per);

    cudaFuncSetAttribute(k_main, cudaFuncAttributeMaxDynamicSharedMemorySize,
                         NSTAGE * STAGEBYTES);
    k_main<<<NN / GG, 128, NSTAGE * STAGEBYTES>>>(idx, coff, ltr, tv, out);
}

// round 6
// speedup vs baseline: 1.0488x; 1.0488x over previous
#include <cuda_runtime.h>
#include <cuda_bf16.h>
#include <cstdint>
#include <math.h>

#define NN 30000
#define KK 15
#define TT 400
#define NCC 5
#define GG 8                      // rows per block in main kernel
#define TMA_ROWS 10               // neighbor rows k=0..9 via TMA
#define LDG_ROWS 6                // self + neighbor rows k=10..14 via LDG
#define ROWBYTES (TT * 2)         // 800 B per bf16 row
#define STAGEBYTES (TMA_ROWS * ROWBYTES)  // 8000 B
#define T4 (TT / 4)               // 100 chunks of 4 t-values

// ---------------- scratch (device globals: allocation-free) ----------------
__device__ __align__(32) __nv_bfloat16 g_emd[NN * TT];  // summed EMD bf16 (24 MB)
__device__ float g_W[NN * 16];        // [0]=(1-ew), [1..15]=combined nbr weights
__device__ float g_UV[NN * 10];       // u[5], v[5]
__device__ float g_tab[2 * NCC * TT]; // sin table, then cos table (fp32)

// ---------------- helpers ----------------
__device__ __forceinline__ uint32_t smem_u32(const void* p) {
    uint32_t a;
    asm("{ .reg .u64 t; cvta.to.shared.u64 t, %1; cvt.u32.u64 %0, t; }"
        : "=r"(a) : "l"(p));
    return a;
}
__device__ __forceinline__ void mbar_init(uint32_t mbar, uint32_t count) {
    asm volatile("mbarrier.init.shared.b64 [%0], %1;" :: "r"(mbar), "r"(count) : "memory");
}
__device__ __forceinline__ void mbar_expect_tx(uint32_t mbar, uint32_t bytes) {
    asm volatile("mbarrier.arrive.expect_tx.shared.b64 _, [%0], %1;"
                 :: "r"(mbar), "r"(bytes) : "memory");
}
__device__ __forceinline__ void mbar_wait(uint32_t mbar, uint32_t parity) {
    asm volatile(
        "{\n\t"
        ".reg .pred P;\n\t"
        "LAB_WAIT_%=:\n\t"
        "mbarrier.try_wait.parity.acquire.cta.shared::cta.b64 P, [%0], %1, 0x989680;\n\t"
        "@P bra LAB_DONE_%=;\n\t"
        "bra LAB_WAIT_%=;\n\t"
        "LAB_DONE_%=:\n\t"
        "}"
        :: "r"(mbar), "r"(parity) : "memory");
}
__device__ __forceinline__ void bulk_g2s(uint32_t dst, const void* src,
                                         uint32_t bytes, uint32_t mbar) {
    asm volatile(
        "cp.async.bulk.shared::cluster.global.mbarrier::complete_tx::bytes "
        "[%0], [%1], %2, [%3];"
        :: "r"(dst), "l"(src), "r"(bytes), "r"(mbar) : "memory");
}
// bf16 unpack: lo via shift; hi uses raw word (garbage low bits below bf16 ulp)
__device__ __forceinline__ float bf_lo(uint32_t u) { return __uint_as_float(u << 16); }
__device__ __forceinline__ float bf_hi(uint32_t u) { return __uint_as_float(u); }

// ---------------- k_pre0: weights + uv + table (small, runs first) ----------
#define NB_W      ((NN * 16 + 255) / 256)
#define NB_UV     ((NN * NCC + 255) / 256)
#define NB_TAB    ((NCC * TT + 255) / 256)
#define NB_PRE0   (NB_W + NB_UV + NB_TAB)

__global__ void __launch_bounds__(256)
k_pre0(const float* __restrict__ nbr_w,
       const float* __restrict__ loc_w,
       const float* __restrict__ esw,
       const float* __restrict__ lsw,
       const float* __restrict__ amp,
       const float* __restrict__ ph,
       const int*   __restrict__ idx,
       const float* __restrict__ tv,
       const float* __restrict__ per) {
    int b = blockIdx.x;
    if (b < NB_W) {
        int i = b * 256 + threadIdx.x;
        if (i >= NN * 16) return;
        int n = i >> 4;
        int j = i & 15;
        float ew = 1.0f / (1.0f + expf(-esw[n]));
        if (j == 0) { g_W[i] = 1.0f - ew; return; }
        float lw = 1.0f / (1.0f + expf(-lsw[n]));
        int k = j - 1;
        g_W[i] = ew * lw * loc_w[n * KK + k] + ew * (1.0f - lw) * nbr_w[n * KK + k];
        return;
    }
    b -= NB_W;
    if (b < NB_UV) {
        int i = b * 256 + threadIdx.x;
        if (i >= NN * NCC) return;
        int n = i / NCC;
        int c = i - n * NCC;
        float sa = 0.0f, ss = 0.0f, sc = 0.0f;
#pragma unroll
        for (int k = 0; k < KK; k++) {
            int m = idx[n * KK + k];
            float w = nbr_w[n * KK + k];
            sa += w * amp[m * NCC + c];
            float p = ph[m * NCC + c];
            float s, co;
            sincosf(p, &s, &co);
            ss += w * s;
            sc += w * co;
        }
        float A = 0.8f * amp[i] + 0.2f * sa;
        float P = 0.8f * ph[i] + 0.2f * atan2f(ss, sc);
        float sp, cp;
        sincosf(P, &sp, &cp);
        g_UV[n * 10 + c] = A * cp;
        g_UV[n * 10 + 5 + c] = A * sp;
        return;
    }
    b -= NB_UV;
    {
        int i = b * 256 + threadIdx.x;
        if (i >= NCC * TT) return;
        int c = i / TT;
        int t = i - c * TT;
        float p = fminf(fmaxf(per[c], 15.0f), 350.0f);
        float arg = 6.283185307179586f * tv[t] / p;
        float s, co;
        sincosf(arg, &s, &co);
        g_tab[i] = s;
        g_tab[NCC * TT + i] = co;
    }
}

// ------- k_pre1: baseline -> out (fp32) ∥ emdsum -> g_emd (bf16) ------------
#define BASE_WORK (NN * T4)                  // 3,000,000 float4-groups
#define NB_BASE   ((BASE_WORK + 255) / 256)  // 11719
#define EMD_WORK  (NN * (TT / 8))
#define NB_EMD    ((EMD_WORK + 255) / 256)
#define NB_PRE1   (NB_BASE + NB_EMD)

__global__ void __launch_bounds__(256)
k_pre1(const float* __restrict__ emd,
       const float* __restrict__ coff,
       const float* __restrict__ ltr,
       const float* __restrict__ tv,
       float* __restrict__ out) {
    int b = blockIdx.x;
    if (b < NB_BASE) {
        // ---- baseline: out = offset + trend*t + harmonics ----
        int i = b * 256 + threadIdx.x;
        if (i >= BASE_WORK) return;
        int n = i / T4;
        int t4 = i - n * T4;
        float4 tvv = reinterpret_cast<const float4*>(tv)[t4];
        float off = coff[n], tr = ltr[n];
        float4 acc;
        acc.x = fmaf(tr, tvv.x, off);
        acc.y = fmaf(tr, tvv.y, off);
        acc.z = fmaf(tr, tvv.z, off);
        acc.w = fmaf(tr, tvv.w, off);
        const float* uv = g_UV + n * 10;
#pragma unroll
        for (int c = 0; c < NCC; c++) {
            float u = uv[c], v = uv[5 + c];
            float4 st = reinterpret_cast<const float4*>(g_tab + c * TT)[t4];
            float4 ct = reinterpret_cast<const float4*>(g_tab + NCC * TT + c * TT)[t4];
            acc.x = fmaf(u, st.x, fmaf(v, ct.x, acc.x));
            acc.y = fmaf(u, st.y, fmaf(v, ct.y, acc.y));
            acc.z = fmaf(u, st.z, fmaf(v, ct.z, acc.z));
            acc.w = fmaf(u, st.w, fmaf(v, ct.w, acc.w));
        }
        reinterpret_cast<float4*>(out + (size_t)n * TT)[t4] = acc;
        return;
    }
    b -= NB_BASE;
    {
        // ---- emdsum -> bf16 ----
        int i = b * 256 + threadIdx.x;
        if (i >= EMD_WORK) return;
        int n = i / (TT / 8);
        int t8 = i - n * (TT / 8);
        const float4* base = reinterpret_cast<const float4*>(emd + (size_t)n * 4 * TT);
        float r[8];
#pragma unroll
        for (int e = 0; e < 8; e++) r[e] = 0.0f;
#pragma unroll
        for (int c = 0; c < 4; c++) {
            float4 a = base[c * T4 + 2 * t8];
            float4 bb = base[c * T4 + 2 * t8 + 1];
            r[0] += a.x;  r[1] += a.y;  r[2] += a.z;  r[3] += a.w;
            r[4] += bb.x; r[5] += bb.y; r[6] += bb.z; r[7] += bb.w;
        }
        __nv_bfloat162 h[4];
#pragma unroll
        for (int e = 0; e < 4; e++)
            h[e] = __floats2bfloat162_rn(r[2 * e], r[2 * e + 1]);
        reinterpret_cast<uint4*>(g_emd + (size_t)n * TT)[t8] =
            *reinterpret_cast<uint4*>(h);
    }
}

// ------- k_main: hybrid TMA(10) + LDG(6) gather, RMW onto out ---------------
extern __shared__ __align__(16) __nv_bfloat16 s_buf[];  // 2 * 8000 B

__global__ void __launch_bounds__(128, 9)
k_main(const int* __restrict__ idx, float* __restrict__ out) {
    __shared__ __align__(8) unsigned long long s_full[2];
    __shared__ int   s_idx[GG][KK];
    __shared__ float s_W[GG][16];

    int tid = threadIdx.x;
    int n0 = blockIdx.x * GG;

    if (tid < GG * KK) s_idx[tid / KK][tid % KK] = idx[n0 * KK + tid];
    if (tid < GG * 16) s_W[tid >> 4][tid & 15] = g_W[n0 * 16 + tid];

    uint32_t full0 = smem_u32(&s_full[0]);
    uint32_t bufb  = smem_u32(s_buf);
    if (tid == 0) {
        mbar_init(full0, 1);
        mbar_init(full0 + 8, 1);
        asm volatile("fence.proxy.async.shared::cta;" ::: "memory");
    }
    __syncthreads();  // s_idx/s_W visible; mbarriers initialized

    auto issue = [&](int s) {
        uint32_t dst = bufb + (uint32_t)(s & 1) * STAGEBYTES;
        uint32_t mb  = full0 + (uint32_t)(s & 1) * 8;
        mbar_expect_tx(mb, STAGEBYTES);
#pragma unroll
        for (int k = 0; k < TMA_ROWS; k++) {
            bulk_g2s(dst + (uint32_t)k * ROWBYTES,
                     g_emd + (size_t)s_idx[s][k] * TT, ROWBYTES, mb);
        }
    };

    if (tid == 0) issue(0);

    bool act = (tid < T4);

    for (int i = 0; i < GG; i++) {
        if (tid == 0 && i + 1 < GG) issue(i + 1);

        uint2 raw[LDG_ROWS];
        float4 acc;
        int n = n0 + i;
        if (act) {
            // independent LDG path: self row + neighbors k=10..14 + baseline
            raw[0] = *reinterpret_cast<const uint2*>(g_emd + (size_t)n * TT + 4 * tid);
#pragma unroll
            for (int r = 0; r < 5; r++) {
                int m = s_idx[i][10 + r];
                raw[1 + r] = *reinterpret_cast<const uint2*>(
                    g_emd + (size_t)m * TT + 4 * tid);
            }
            acc = reinterpret_cast<const float4*>(out + (size_t)n * TT)[tid];
        }

        mbar_wait(full0 + (uint32_t)(i & 1) * 8, (uint32_t)((i >> 1) & 1));

        if (act) {
            const uint32_t* rows = reinterpret_cast<const uint32_t*>(
                s_buf + (size_t)(i & 1) * (TMA_ROWS * TT));
            // smem rows: neighbors k=0..9 (weights s_W[i][1..10])
#pragma unroll
            for (int j = 0; j < TMA_ROWS; j++) {
                uint2 rr = *reinterpret_cast<const uint2*>(rows + j * 200 + 2 * tid);
                float w = s_W[i][1 + j];
                acc.x = fmaf(w, bf_lo(rr.x), acc.x);
                acc.y = fmaf(w, bf_hi(rr.x), acc.y);
                acc.z = fmaf(w, bf_lo(rr.y), acc.z);
                acc.w = fmaf(w, bf_hi(rr.y), acc.w);
            }
            // LDG rows: self (w[0]) then k=10..14 (w[11..15])
            {
                float w = s_W[i][0];
                acc.x = fmaf(w, bf_lo(raw[0].x), acc.x);
                acc.y = fmaf(w, bf_hi(raw[0].x), acc.y);
                acc.z = fmaf(w, bf_lo(raw[0].y), acc.z);
                acc.w = fmaf(w, bf_hi(raw[0].y), acc.w);
            }
#pragma unroll
            for (int r = 0; r < 5; r++) {
                float w = s_W[i][11 + r];
                acc.x = fmaf(w, bf_lo(raw[1 + r].x), acc.x);
                acc.y = fmaf(w, bf_hi(raw[1 + r].x), acc.y);
                acc.z = fmaf(w, bf_lo(raw[1 + r].y), acc.z);
                acc.w = fmaf(w, bf_hi(raw[1 + r].y), acc.w);
            }
            reinterpret_cast<float4*>(out + (size_t)n * TT)[tid] = acc;
        }
        __syncthreads();  // all threads done reading smem buffer i&1
    }
}

// ---------------- launch ----------------
extern "C" void kernel_launch(void* const* d_in, const int* in_sizes, int n_in,
                              void* d_out, int out_size) {
    const float* tv   = (const float*)d_in[0];
    const float* coff = (const float*)d_in[1];
    const float* ltr  = (const float*)d_in[2];
    const float* emd  = (const float*)d_in[3];
    const int*   idx  = (const int*)  d_in[4];
    const float* nw   = (const float*)d_in[5];
    const float* lwv  = (const float*)d_in[6];
    const float* amp  = (const float*)d_in[7];
    const float* ph   = (const float*)d_in[8];
    const float* per  = (const float*)d_in[9];
    const float* esw  = (const float*)d_in[10];
    const float* lsw  = (const float*)d_in[11];
    float* out = (float*)d_out;

    k_pre0<<<NB_PRE0, 256>>>(nw, lwv, esw, lsw, amp, ph, idx, tv, per);
    k_pre1<<<NB_PRE1, 256>>>(emd, coff, ltr, tv, out);
    k_main<<<NN / GG, 128, 2 * STAGEBYTES>>>(idx, out);
}

// round 7
// speedup vs baseline: 1.2261x; 1.1690x over previous
#include <cuda_runtime.h>
#include <cuda_bf16.h>
#include <cstdint>
#include <math.h>

#define NN 30000
#define KK 15
#define TT 400
#define NCC 5
#define GG 8                      // rows per block in main kernel
#define ROWS 16                   // self + 15 neighbors
#define ROWBYTES (TT * 2)         // 800 B per bf16 row
#define STAGEBYTES (ROWS * ROWBYTES)  // 12800 B
#define T4 (TT / 4)               // 100 chunks of 4 t-values

// ---------------- scratch (device globals: allocation-free) ----------------
__device__ __align__(32) __nv_bfloat16 g_emd[NN * TT];  // summed EMD bf16 (24 MB)
__device__ float g_W[NN * 16];
__device__ float g_UV[NN * 10];
__device__ float g_tab[2 * NCC * TT];

// ---------------- helpers ----------------
__device__ __forceinline__ uint32_t smem_u32(const void* p) {
    uint32_t a;
    asm("{ .reg .u64 t; cvta.to.shared.u64 t, %1; cvt.u32.u64 %0, t; }"
        : "=r"(a) : "l"(p));
    return a;
}
__device__ __forceinline__ void mbar_init(uint32_t mbar, uint32_t count) {
    asm volatile("mbarrier.init.shared.b64 [%0], %1;" :: "r"(mbar), "r"(count) : "memory");
}
__device__ __forceinline__ void mbar_expect_tx(uint32_t mbar, uint32_t bytes) {
    asm volatile("mbarrier.arrive.expect_tx.shared.b64 _, [%0], %1;"
                 :: "r"(mbar), "r"(bytes) : "memory");
}
__device__ __forceinline__ void mbar_wait(uint32_t mbar, uint32_t parity) {
    asm volatile(
        "{\n\t"
        ".reg .pred P;\n\t"
        "LAB_WAIT_%=:\n\t"
        "mbarrier.try_wait.parity.acquire.cta.shared::cta.b64 P, [%0], %1, 0x989680;\n\t"
        "@P bra LAB_DONE_%=;\n\t"
        "bra LAB_WAIT_%=;\n\t"
        "LAB_DONE_%=:\n\t"
        "}"
        :: "r"(mbar), "r"(parity) : "memory");
}
__device__ __forceinline__ void bulk_g2s(uint32_t dst, const void* src,
                                         uint32_t bytes, uint32_t mbar) {
    asm volatile(
        "cp.async.bulk.shared::cluster.global.mbarrier::complete_tx::bytes "
        "[%0], [%1], %2, [%3];"
        :: "r"(dst), "l"(src), "r"(bytes), "r"(mbar) : "memory");
}
// bf16 unpack: lo via shift; hi uses raw word (garbage low bits below bf16 ulp;
// measured rel_err 2.2e-4 vs 1e-3 threshold)
__device__ __forceinline__ float bf_lo(uint32_t u) { return __uint_as_float(u << 16); }
__device__ __forceinline__ float bf_hi(uint32_t u) { return __uint_as_float(u); }

// ------------- fused pre-pass: UV (longest latency) FIRST, emdsum last ------
#define EMD_WORK  (NN * (TT / 8))
#define NB_EMD    ((EMD_WORK + 255) / 256)
#define NB_W      ((NN * 16 + 255) / 256)
#define NB_UV     ((NN * NCC + 255) / 256)
#define NB_TAB    ((NCC * TT + 255) / 256)
#define NB_PRE    (NB_EMD + NB_W + NB_UV + NB_TAB)

__global__ void __launch_bounds__(256)
k_pre(const float* __restrict__ emd,
      const float* __restrict__ nbr_w,
      const float* __restrict__ loc_w,
      const float* __restrict__ esw,
      const float* __restrict__ lsw,
      const float* __restrict__ amp,
      const float* __restrict__ ph,
      const int*   __restrict__ idx,
      const float* __restrict__ tv,
      const float* __restrict__ per) {
    int b = blockIdx.x;
    if (b < NB_UV) {
        // ---- smoothed residual params -> u,v (latency-heavy, start first) ----
        int i = b * 256 + threadIdx.x;
        if (i >= NN * NCC) return;
        int n = i / NCC;
        int c = i - n * NCC;
        float sa = 0.0f, ss = 0.0f, sc = 0.0f;
#pragma unroll
        for (int k = 0; k < KK; k++) {
            int m = idx[n * KK + k];
            float w = nbr_w[n * KK + k];
            sa += w * amp[m * NCC + c];
            float p = ph[m * NCC + c];
            float s, co;
            __sincosf(p, &s, &co);
            ss += w * s;
            sc += w * co;
        }
        float A = 0.8f * amp[i] + 0.2f * sa;
        float P = 0.8f * ph[i] + 0.2f * atan2f(ss, sc);
        float sp, cp;
        __sincosf(P, &sp, &cp);
        g_UV[n * 10 + c] = A * cp;
        g_UV[n * 10 + 5 + c] = A * sp;
        return;
    }
    b -= NB_UV;
    if (b < NB_W) {
        int i = b * 256 + threadIdx.x;
        if (i >= NN * 16) return;
        int n = i >> 4;
        int j = i & 15;
        float ew = 1.0f / (1.0f + __expf(-esw[n]));
        if (j == 0) { g_W[i] = 1.0f - ew; return; }
        float lw = 1.0f / (1.0f + __expf(-lsw[n]));
        int k = j - 1;
        g_W[i] = ew * lw * loc_w[n * KK + k] + ew * (1.0f - lw) * nbr_w[n * KK + k];
        return;
    }
    b -= NB_W;
    if (b < NB_TAB) {
        // table: keep accurate sincosf (t/period up to ~167 rad, outside fast range)
        int i = b * 256 + threadIdx.x;
        if (i >= NCC * TT) return;
        int c = i / TT;
        int t = i - c * TT;
        float p = fminf(fmaxf(per[c], 15.0f), 350.0f);
        float arg = 6.283185307179586f * tv[t] / p;
        float s, co;
        sincosf(arg, &s, &co);
        g_tab[i] = s;
        g_tab[NCC * TT + i] = co;
        return;
    }
    b -= NB_TAB;
    {
        // ---- sum 4 EMD components, write bf16 (DRAM-bound bulk) ----
        int i = b * 256 + threadIdx.x;
        if (i >= EMD_WORK) return;
        int n = i / (TT / 8);
        int t8 = i - n * (TT / 8);
        const float4* base = reinterpret_cast<const float4*>(emd + (size_t)n * 4 * TT);
        float r[8];
#pragma unroll
        for (int e = 0; e < 8; e++) r[e] = 0.0f;
#pragma unroll
        for (int c = 0; c < 4; c++) {
            float4 a = base[c * T4 + 2 * t8];
            float4 bb = base[c * T4 + 2 * t8 + 1];
            r[0] += a.x;  r[1] += a.y;  r[2] += a.z;  r[3] += a.w;
            r[4] += bb.x; r[5] += bb.y; r[6] += bb.z; r[7] += bb.w;
        }
        __nv_bfloat162 h[4];
#pragma unroll
        for (int e = 0; e < 4; e++)
            h[e] = __floats2bfloat162_rn(r[2 * e], r[2 * e + 1]);
        reinterpret_cast<uint4*>(g_emd + (size_t)n * TT)[t8] =
            *reinterpret_cast<uint4*>(h);
    }
}

// ---------------- main kernel: TMA bf16 row-gather + fused output ----------
extern __shared__ __align__(16) __nv_bfloat16 s_buf[];  // 2 * 12800 B

__global__ void __launch_bounds__(128, 8)   // force <=64 regs -> 8 blocks/SM
k_main(const int* __restrict__ idx,
       const float* __restrict__ coff,
       const float* __restrict__ ltr,
       const float* __restrict__ tv,
       float* __restrict__ out) {
    __shared__ __align__(8) unsigned long long s_full[2];
    __shared__ int   s_idx[GG][KK];
    __shared__ float s_W[GG][16];
    __shared__ float s_UV[GG][10];
    __shared__ float s_off[GG];
    __shared__ float s_tr[GG];

    int tid = threadIdx.x;
    int n0 = blockIdx.x * GG;

    if (tid < GG * KK) s_idx[tid / KK][tid % KK] = idx[n0 * KK + tid];
    if (tid < GG * 16) s_W[tid >> 4][tid & 15] = g_W[n0 * 16 + tid];
    if (tid < GG * 10) s_UV[tid / 10][tid % 10] = g_UV[n0 * 10 + tid];
    if (tid < GG) { s_off[tid] = coff[n0 + tid]; s_tr[tid] = ltr[n0 + tid]; }

    uint32_t full0 = smem_u32(&s_full[0]);
    uint32_t bufb  = smem_u32(s_buf);
    if (tid == 0) {
        mbar_init(full0, 1);
        mbar_init(full0 + 8, 1);
        asm volatile("fence.proxy.async.shared::cta;" ::: "memory");
    }

    // per-thread register-resident harmonic table + time values (fp32)
    float4 st[NCC], ct[NCC], tv4;
    bool act = (tid < T4);
    if (act) {
#pragma unroll
        for (int c = 0; c < NCC; c++) {
            st[c] = reinterpret_cast<const float4*>(g_tab + c * TT)[tid];
            ct[c] = reinterpret_cast<const float4*>(g_tab + NCC * TT + c * TT)[tid];
        }
        tv4 = reinterpret_cast<const float4*>(tv)[tid];
    }
    __syncthreads();  // s_idx visible; mbarriers initialized

    auto issue = [&](int s) {
        uint32_t dst = bufb + (uint32_t)(s & 1) * STAGEBYTES;
        uint32_t mb  = full0 + (uint32_t)(s & 1) * 8;
        mbar_expect_tx(mb, STAGEBYTES);
        bulk_g2s(dst, g_emd + (size_t)(n0 + s) * TT, ROWBYTES, mb);  // self row
#pragma unroll
        for (int k = 0; k < KK; k++) {
            bulk_g2s(dst + (uint32_t)(k + 1) * ROWBYTES,
                     g_emd + (size_t)s_idx[s][k] * TT, ROWBYTES, mb);
        }
    };

    if (tid == 0) issue(0);

    for (int i = 0; i < GG; i++) {
        if (tid == 0 && i + 1 < GG) issue(i + 1);
        mbar_wait(full0 + (uint32_t)(i & 1) * 8, (uint32_t)((i >> 1) & 1));

        if (act) {
            const uint32_t* rows = reinterpret_cast<const uint32_t*>(
                s_buf + (size_t)(i & 1) * (ROWS * TT));

            float off = s_off[i], tr = s_tr[i];
            float4 acc;
            acc.x = fmaf(tr, tv4.x, off);
            acc.y = fmaf(tr, tv4.y, off);
            acc.z = fmaf(tr, tv4.z, off);
            acc.w = fmaf(tr, tv4.w, off);
#pragma unroll
            for (int c = 0; c < NCC; c++) {
                float u = s_UV[i][c], v = s_UV[i][5 + c];
                acc.x = fmaf(u, st[c].x, fmaf(v, ct[c].x, acc.x));
                acc.y = fmaf(u, st[c].y, fmaf(v, ct[c].y, acc.y));
                acc.z = fmaf(u, st[c].z, fmaf(v, ct[c].z, acc.z));
                acc.w = fmaf(u, st[c].w, fmaf(v, ct[c].w, acc.w));
            }
#pragma unroll
            for (int j = 0; j < 16; j++) {
                uint2 raw = *reinterpret_cast<const uint2*>(rows + j * 200 + 2 * tid);
                float w = s_W[i][j];
                acc.x = fmaf(w, bf_lo(raw.x), acc.x);
                acc.y = fmaf(w, bf_hi(raw.x), acc.y);
                acc.z = fmaf(w, bf_lo(raw.y), acc.z);
                acc.w = fmaf(w, bf_hi(raw.y), acc.w);
            }
            reinterpret_cast<float4*>(out + (size_t)(n0 + i) * TT)[tid] = acc;
        }
        __syncthreads();  // all threads done reading buffer i&1
    }
}

// ---------------- launch ----------------
extern "C" void kernel_launch(void* const* d_in, const int* in_sizes, int n_in,
                              void* d_out, int out_size) {
    const float* tv   = (const float*)d_in[0];
    const float* coff = (const float*)d_in[1];
    const float* ltr  = (const float*)d_in[2];
    const float* emd  = (const float*)d_in[3];
    const int*   idx  = (const int*)  d_in[4];
    const float* nw   = (const float*)d_in[5];
    const float* lwv  = (const float*)d_in[6];
    const float* amp  = (const float*)d_in[7];
    const float* ph   = (const float*)d_in[8];
    const float* per  = (const float*)d_in[9];
    const float* esw  = (const float*)d_in[10];
    const float* lsw  = (const float*)d_in[11];
    float* out = (float*)d_out;

    k_pre<<<NB_PRE, 256>>>(emd, nw, lwv, esw, lsw, amp, ph, idx, tv, per);

    cudaFuncSetAttribute(k_main, cudaFuncAttributeMaxDynamicSharedMemorySize,
                         2 * STAGEBYTES);
    k_main<<<NN / GG, 128, 2 * STAGEBYTES>>>(idx, coff, ltr, tv, out);
}